// round 15
// baseline (speedup 1.0000x reference)
#include <cuda_runtime.h>
#include <math.h>
#include <stdint.h>

// ChordalPCWeightTransform — R11: TMA bulk load + per-thread streaming stores.
// Math identity (R4): the two per-label rolls cancel on the data and rotate
// only the weight vector:
//   out[b,l,p] = softmax_p( x[b,l,p] * w[(p - root) mod 12] ), p<12; w[12] at p=12
//   root = (row / 12) % 12
//
// Load side (from R10): one 26624 B cp.async.bulk per CTA — contiguous DRAM
// bursts, no per-thread staging traffic. Store side (from R9): __stcs float4
// stores, fire-and-forget, so CTAs retire without waiting for a TMA store
// drain (removes R10's tail serialization).

#define P 13
#define RPB 256
#define ROWS_PER_TILE 512
#define TILE_FLOATS (ROWS_PER_TILE * P)     // 6656 floats = 26624 B
#define TILE_BYTES (TILE_FLOATS * 4)
#define VEC4_PER_TILE (TILE_FLOATS / 4)     // 1664 = 6.5 * 256

__global__ __launch_bounds__(RPB)
void chordal_softmax_kernel(const float* __restrict__ x,
                            const float* __restrict__ w,
                            float* __restrict__ out)
{
    __shared__ alignas(128) float tile[TILE_FLOATS];
    __shared__ float ws[P];
    __shared__ alignas(8) uint64_t mbar;

    const int tid = threadIdx.x;
    if (tid < P) ws[tid] = __ldg(&w[tid]);

    const uint32_t mbar_a = (uint32_t)__cvta_generic_to_shared(&mbar);
    const uint32_t tile_a = (uint32_t)__cvta_generic_to_shared(tile);
    const long long base = (long long)blockIdx.x * TILE_FLOATS;

    if (tid == 0) {
        asm volatile("mbarrier.init.shared.b64 [%0], 1;" :: "r"(mbar_a) : "memory");
    }
    __syncthreads();

    // ---- single bulk load: global -> smem (26624 B, one TMA op) ----
    if (tid == 0) {
        asm volatile("mbarrier.arrive.expect_tx.shared.b64 _, [%0], %1;"
                     :: "r"(mbar_a), "r"((uint32_t)TILE_BYTES) : "memory");
        asm volatile("cp.async.bulk.shared::cta.global.mbarrier::complete_tx::bytes "
                     "[%0], [%1], %2, [%3];"
                     :: "r"(tile_a), "l"(x + base), "r"((uint32_t)TILE_BYTES),
                        "r"(mbar_a) : "memory");
    }
    // all threads wait for completion (phase 0)
    {
        uint32_t done;
        asm volatile(
            "{\n\t"
            ".reg .pred p;\n\t"
            "mbarrier.try_wait.parity.acquire.cta.shared::cta.b64 p, [%1], 0;\n\t"
            "selp.b32 %0, 1, 0, p;\n\t"
            "}" : "=r"(done) : "r"(mbar_a) : "memory");
        if (!done) {
            asm volatile(
                "{\n\t"
                ".reg .pred P1;\n\t"
                "WL_%=:\n\t"
                "mbarrier.try_wait.parity.acquire.cta.shared::cta.b64 P1, [%0], 0, 0x989680;\n\t"
                "@P1 bra.uni WD_%=;\n\t"
                "bra.uni WL_%=;\n\t"
                "WD_%=:\n\t"
                "}" :: "r"(mbar_a) : "memory");
        }
    }
    __syncthreads();

    // ---- per-thread weighted softmax, 2 rows per thread, in place ----
#pragma unroll
    for (int rr = 0; rr < 2; rr++) {
        const int lr   = tid + rr * RPB;                 // local row 0..511
        const int row  = blockIdx.x * ROWS_PER_TILE + lr;
        const int root = (row / 12) % 12;

        float v[P];
        float m = -INFINITY;
#pragma unroll
        for (int p = 0; p < P; p++) {
            int wi;
            if (p == 12) {
                wi = 12;
            } else {
                wi = p - root;
                if (wi < 0) wi += 12;
            }
            v[p] = tile[lr * P + p] * ws[wi];
            m = fmaxf(m, v[p]);
        }
        float s = 0.0f;
#pragma unroll
        for (int p = 0; p < P; p++) { v[p] = __expf(v[p] - m); s += v[p]; }
        const float r = __frcp_rn(s);
#pragma unroll
        for (int p = 0; p < P; p++) tile[lr * P + p] = v[p] * r;
    }
    __syncthreads();   // all rows written before vectorized readback

    // ---- vectorized streaming store: smem -> global (fire-and-forget) ----
    // 1664 vec4 = 6 full 256-thread iterations + 128-thread remainder.
    {
        float4* go = (float4*)(out + base);
        const float4* sv = (const float4*)tile;
#pragma unroll
        for (int i = 0; i < 6; i++) {
            const int idx = tid + i * RPB;
            __stcs(&go[idx], sv[idx]);
        }
        if (tid < (VEC4_PER_TILE - 6 * RPB)) {           // 128 remainder
            const int idx = tid + 6 * RPB;
            __stcs(&go[idx], sv[idx]);
        }
    }
}

extern "C" void kernel_launch(void* const* d_in, const int* in_sizes, int n_in,
                              void* d_out, int out_size)
{
    const float* x = (const float*)d_in[0];   // chordal_pc_vector [65536,144,13]
    const float* w = (const float*)d_in[1];   // scale_degree_weight [13]
    float* out = (float*)d_out;

    const long long total = (long long)in_sizes[0];   // 122,683,392
    const int nblocks = (int)(total / TILE_FLOATS);   // 18432

    // Full smem carveout so 8 CTAs/SM fit (8 * ~26.8 KB).
    cudaFuncSetAttribute(chordal_softmax_kernel,
                         cudaFuncAttributePreferredSharedMemoryCarveout, 100);

    chordal_softmax_kernel<<<nblocks, RPB>>>(x, w, out);
}

// round 16
// speedup vs baseline: 1.0212x; 1.0212x over previous
#include <cuda_runtime.h>
#include <math.h>
#include <stdint.h>

// ChordalPCWeightTransform — R15: eager cp.async loads + TMA bulk burst store.
// Math identity (R4): the two per-label rolls cancel on the data and rotate
// only the weight vector:
//   out[b,l,p] = softmax_p( x[b,l,p] * w[(p - root) mod 12] ), p<12; w[12] at p=12
//   root = (row / 12) % 12
//
// Front end = R9 (best-overlap loads: 13 eager cp.async.cg per thread, 256-row
// tile, occ ~94%). Back end = R10's winner (single 13312 B cp.async.bulk
// smem->global per CTA: one contiguous full-line burst instead of ~832
// scattered 16 B stores).

#define P 13
#define RPB 256
#define TILE_FLOATS (RPB * P)            // 3328 floats = 13312 B (mult of 16)
#define TILE_BYTES (TILE_FLOATS * 4)

__device__ __forceinline__ void cp_async16(uint32_t saddr, const void* gptr) {
    asm volatile("cp.async.cg.shared.global [%0], [%1], 16;"
                 :: "r"(saddr), "l"(gptr));
}

__global__ __launch_bounds__(RPB)
void chordal_softmax_kernel(const float* __restrict__ x,
                            const float* __restrict__ w,
                            float* __restrict__ out)
{
    __shared__ alignas(128) float tile[TILE_FLOATS];
    __shared__ float ws[P];

    const int tid = threadIdx.x;
    if (tid < P) ws[tid] = __ldg(&w[tid]);

    const long long base = (long long)blockIdx.x * TILE_FLOATS;
    const uint32_t tile_a = (uint32_t)__cvta_generic_to_shared(tile);

    // ---- eager async staging: global -> smem (R9 path, full MLP) ----
    {
        const float4* g = (const float4*)(x + base);
        cp_async16(tile_a + (uint32_t)(tid)       * 16, g + tid);
        cp_async16(tile_a + (uint32_t)(tid + 256) * 16, g + tid + 256);
        cp_async16(tile_a + (uint32_t)(tid + 512) * 16, g + tid + 512);
        if (tid < 64)
            cp_async16(tile_a + (uint32_t)(tid + 768) * 16, g + tid + 768);
        asm volatile("cp.async.commit_group;");
        asm volatile("cp.async.wait_group 0;");
    }
    __syncthreads();

    // ---- per-row weighted softmax (thread owns one row, in place) ----
    const int row  = blockIdx.x * RPB + tid;
    const int root = (row / 12) % 12;

    float v[P];
    float m = -INFINITY;
#pragma unroll
    for (int p = 0; p < P; p++) {
        int wi;
        if (p == 12) {
            wi = 12;
        } else {
            wi = p - root;
            if (wi < 0) wi += 12;
        }
        v[p] = tile[tid * P + p] * ws[wi];
        m = fmaxf(m, v[p]);
    }

    float s = 0.0f;
#pragma unroll
    for (int p = 0; p < P; p++) { v[p] = __expf(v[p] - m); s += v[p]; }
    const float r = __frcp_rn(s);

    // Thread overwrites only its own 13 floats — no barrier needed here.
#pragma unroll
    for (int p = 0; p < P; p++) tile[tid * P + p] = v[p] * r;
    __syncthreads();   // all rows in smem before the bulk store reads them

    // ---- single bulk burst store: smem -> global (13312 B, one TMA op) ----
    if (tid == 0) {
        asm volatile("fence.proxy.async.shared::cta;" ::: "memory");
        asm volatile("cp.async.bulk.global.shared::cta.bulk_group [%0], [%1], %2;"
                     :: "l"(out + base), "r"(tile_a), "r"((uint32_t)TILE_BYTES)
                     : "memory");
        asm volatile("cp.async.bulk.commit_group;");
        // smem must stay live until the TMA engine has read it out.
        asm volatile("cp.async.bulk.wait_group.read 0;" ::: "memory");
    }
}

extern "C" void kernel_launch(void* const* d_in, const int* in_sizes, int n_in,
                              void* d_out, int out_size)
{
    const float* x = (const float*)d_in[0];   // chordal_pc_vector [65536,144,13]
    const float* w = (const float*)d_in[1];   // scale_degree_weight [13]
    float* out = (float*)d_out;

    const long long total = (long long)in_sizes[0];   // 122,683,392
    const int nblocks = (int)(total / TILE_FLOATS);   // 36864

    chordal_softmax_kernel<<<nblocks, RPB>>>(x, w, out);
}